// round 12
// baseline (speedup 1.0000x reference)
#include <cuda_runtime.h>
#include <cuda_bf16.h>
#include <cstdint>

// Problem constants
#define NB 8
#define NL 2048
#define ND 128
#define EPSN 1e-8f
#define MARGIN 0.02f
#define CCAP 48

// ---------------- scratch (no allocation allowed) ----------------
__device__ __align__(128) float g_cn[NB * NL * ND];            // normalized ctx
__device__ __align__(128) float g_en[NB * NL * ND];            // normalized ent
__device__ __align__(128) __nv_bfloat16 g_cnbf[NB * NL * ND];  // bf16(cn)
__device__ __align__(128) __nv_bfloat16 g_enbf[NB * NL * ND];  // bf16(en)
__device__ __align__(128) float g_scn[NB * NL];                // s(cn row)
__device__ __align__(128) float g_sen[NB * NL];                // s(en row)
__device__ __align__(128) int g_idx[NB * NL];

// ---------------- PTX helpers (compute_103-safe) ----------------
__device__ __forceinline__ uint32_t smem_u32(const void* p) {
    uint32_t a;
    asm("{ .reg .u64 t; cvta.to.shared.u64 t, %1; cvt.u32.u64 %0, t; }"
        : "=r"(a) : "l"(p));
    return a;
}
__device__ __forceinline__ void ldm4(uint32_t* a, uint32_t addr) {
    asm volatile("ldmatrix.sync.aligned.m8n8.x4.shared.b16 {%0,%1,%2,%3}, [%4];"
                 : "=r"(a[0]), "=r"(a[1]), "=r"(a[2]), "=r"(a[3]) : "r"(addr));
}
__device__ __forceinline__ void mma16816s(float* c, const uint32_t* a,
                                          uint32_t b0, uint32_t b1) {
    asm volatile(
        "mma.sync.aligned.m16n8k16.row.col.f32.bf16.bf16.f32 "
        "{%0,%1,%2,%3}, {%4,%5,%6,%7}, {%8,%9}, {%0,%1,%2,%3};"
        : "+f"(c[0]), "+f"(c[1]), "+f"(c[2]), "+f"(c[3])
        : "r"(a[0]), "r"(a[1]), "r"(a[2]), "r"(a[3]), "r"(b0), "r"(b1));
}
#define CP_ASYNC16(dst, src) \
    asm volatile("cp.async.cg.shared.global [%0], [%1], 16;" :: "r"(dst), "l"(src))
#define CP_COMMIT() asm volatile("cp.async.commit_group;")
#define CP_WAIT(n)  asm volatile("cp.async.wait_group %0;" :: "n"(n))

// =================================================================
// Stage 1: L2-normalize; emit fp32 rows + bf16 rows (proven, 9.2us).
// =================================================================
__global__ void norm_kernel(const float* __restrict__ ctx) {
    int gwarp = (blockIdx.x * blockDim.x + threadIdx.x) >> 5;
    int lane  = threadIdx.x & 31;
    if (gwarp >= 2 * NB * NL) return;
    int which = gwarp >> 14;
    int r     = gwarp & (NB * NL - 1);
    int b = r >> 11, l = r & (NL - 1);
    const float4* src =
        (const float4*)(ctx + ((size_t)(b * 2 + which) * NL + l) * ND);
    float4 v = src[lane];
    float s = v.x * v.x + v.y * v.y + v.z * v.z + v.w * v.w;
#pragma unroll
    for (int o = 16; o; o >>= 1) s += __shfl_xor_sync(0xffffffffu, s, o);
    float inv = 1.0f / fmaxf(sqrtf(s), EPSN);
    float4 o4 = make_float4(v.x * inv, v.y * inv, v.z * inv, v.w * inv);
    float* dst = which ? g_en : g_cn;
    ((float4*)(dst + (size_t)r * ND))[lane] = o4;

    __nv_bfloat16* bdst = which ? g_enbf : g_cnbf;
    __nv_bfloat162* hp = (__nv_bfloat162*)(bdst + (size_t)r * ND + lane * 4);
    hp[0] = __halves2bfloat162(__float2bfloat16(o4.x), __float2bfloat16(o4.y));
    hp[1] = __halves2bfloat162(__float2bfloat16(o4.z), __float2bfloat16(o4.w));
}

// =================================================================
// Stage 2 (side stream): per-row MLP scalar s(row)=relu(row.W1+b1)@W2
// for all 32768 rows — R8-proven kernel verbatim (53us).
// =================================================================
#define W1S 132
#define SMLP_ROWS (128 * W1S)
#define SMLP_PART (SMLP_ROWS + 16 * 128)
#define SMLP_TOTAL ((SMLP_PART + 64) * 4)

__global__ __launch_bounds__(128) void smlp_kernel(
    const float* __restrict__ W1, const float* __restrict__ b1,
    const float* __restrict__ W2) {
    extern __shared__ float sm[];
    float* W1t  = sm;
    float* rows = sm + SMLP_ROWS;
    float* part = sm + SMLP_PART;

    int tid = threadIdx.x, lane = tid & 31, wp = tid >> 5;

#pragma unroll
    for (int i = 0; i < 128; ++i) {
        int flat = i * 128 + tid;
        int j = flat & 127, k = flat >> 7;
        W1t[j * W1S + k] = W1[k * 128 + j];
    }
    float bias = b1[tid];
    float w2   = W2[tid];

    int r0 = blockIdx.x * 64;
    for (int g0 = 0; g0 < 64; g0 += 16) {
        __syncthreads();
#pragma unroll
        for (int i = 0; i < 16; ++i) {
            int flat = i * 128 + tid;
            int r = flat >> 7, k = flat & 127;
            int vr = r0 + g0 + r;
            const float* src = (vr < NB * NL)
                ? g_cn + (size_t)vr * ND
                : g_en + (size_t)(vr - NB * NL) * ND;
            rows[r * 128 + k] = src[k];
        }
        __syncthreads();

        float acc[16];
#pragma unroll
        for (int r = 0; r < 16; ++r) acc[r] = bias;
#pragma unroll 4
        for (int kq = 0; kq < 32; ++kq) {
            float4 w4 = *(const float4*)(W1t + tid * W1S + kq * 4);
#pragma unroll
            for (int r = 0; r < 16; ++r) {
                float4 x = *(const float4*)(rows + r * 128 + kq * 4);
                acc[r] += w4.x * x.x + w4.y * x.y + w4.z * x.z + w4.w * x.w;
            }
        }
#pragma unroll
        for (int r = 0; r < 16; ++r) {
            float c = fmaxf(acc[r], 0.0f) * w2;
#pragma unroll
            for (int o = 16; o; o >>= 1) c += __shfl_xor_sync(0xffffffffu, c, o);
            if (lane == 0) part[r * 4 + wp] = c;
        }
        __syncthreads();
        if (tid < 16) {
            float s = part[tid * 4] + part[tid * 4 + 1] +
                      part[tid * 4 + 2] + part[tid * 4 + 3];
            int vr = r0 + g0 + tid;
            if (vr < NB * NL) g_scn[vr] = s;
            else              g_sen[vr - NB * NL] = s;
        }
    }
}

// =================================================================
// Stage 3: HMMA sim-GEMM + fused argmax -> g_idx.
// 2-stage pipeline (R3/R5-proven schedule), R11 k-loop, index-only
// candidates + rescore-ALL (R9-proven). smem 131.6KB so smlp (76KB)
// can co-reside on the same SM.
// =================================================================
#define LDB 272
#define SM_AT   0                           // 34816
#define SM_BT0  34816                       // 2 x 34816
#define SM_CI   104448                      // 128*48*4 = 24576
#define SM_CNT  129024                      // 512
#define SM_RED  129536                      // 1024 f + 1024 i
#define SM_SIM_TOTAL 131584

__global__ __launch_bounds__(256, 1) void simarg_kernel() {
    extern __shared__ char smc[];
    int*   candI = (int*)(smc + SM_CI);
    int*   cnt   = (int*)(smc + SM_CNT);
    float* redV  = (float*)(smc + SM_RED);
    int*   redI  = (int*)(smc + SM_RED + 1024);

    int tid = threadIdx.x, w = tid >> 5, lane = tid & 31;
    int wy = w >> 1, wx = w & 1;
    int g = lane >> 2, t = lane & 3;
    int b = blockIdx.y, l0 = blockIdx.x * 128;

    if (tid < 128) cnt[tid] = 0;

    // load A tile (plain vectorized copy)
    const uint4* asrc = (const uint4*)(g_cnbf + ((size_t)b * NL + l0) * ND);
#pragma unroll
    for (int i = tid; i < 2048; i += 256) {
        int row = i >> 4, c = i & 15;
        *(uint4*)(smc + SM_AT + row * LDB + c * 16) = asrc[row * 16 + c];
    }

    const char* esrc = (const char*)(g_enbf + (size_t)b * NL * ND);
    uint32_t sb = smem_u32(smc);

    // prefetch B tile 0
#pragma unroll
    for (int i = tid; i < 2048; i += 256) {
        int row = i >> 4, c = i & 15;
        CP_ASYNC16(sb + SM_BT0 + row * LDB + c * 16,
                   esrc + (size_t)row * 256 + c * 16);
    }
    CP_COMMIT();

    uint32_t aaddr = sb + SM_AT + ((32 * wy + (lane & 15)) * LDB + (lane >> 4) * 16);
    uint32_t boff = (lane & 7) * LDB + ((lane >> 3) & 1) * 16 + (lane >> 4) * 8 * LDB;

    float rmax[2][2] = {{-2.0f, -2.0f}, {-2.0f, -2.0f}};

    for (int mt = 0; mt < 16; ++mt) {
        int cur = mt & 1;
        if (mt + 1 < 16) {
            int nb_ = SM_BT0 + ((mt + 1) & 1) * 34816;
#pragma unroll
            for (int i = tid; i < 2048; i += 256) {
                int row = i >> 4, c = i & 15;
                CP_ASYNC16(sb + nb_ + row * LDB + c * 16,
                           esrc + ((size_t)(mt + 1) * 128 + row) * 256 + c * 16);
            }
            CP_COMMIT();
            CP_WAIT(1);
        } else {
            CP_WAIT(0);
        }
        __syncthreads();

        uint32_t bbase = sb + SM_BT0 + cur * 34816 + boff + wx * 64 * LDB;

        float acc[2][8][4];
#pragma unroll
        for (int f = 0; f < 2; ++f)
#pragma unroll
            for (int j = 0; j < 8; ++j)
#pragma unroll
                for (int c = 0; c < 4; ++c) acc[f][j][c] = 0.0f;

        // fragment-pipelined k-loop (R11)
        uint32_t af[2][2][4];
        uint32_t bf[2][4][4];
        ldm4(af[0][0], aaddr);
        ldm4(af[0][1], aaddr + 16 * LDB);
#pragma unroll
        for (int j2 = 0; j2 < 4; ++j2) ldm4(bf[0][j2], bbase + j2 * 16 * LDB);

#pragma unroll
        for (int kc = 0; kc < 8; ++kc) {
            int cb = kc & 1, nx = cb ^ 1;
            if (kc < 7) {
                ldm4(af[nx][0], aaddr + (kc + 1) * 32);
                ldm4(af[nx][1], aaddr + 16 * LDB + (kc + 1) * 32);
#pragma unroll
                for (int j2 = 0; j2 < 4; ++j2)
                    ldm4(bf[nx][j2], bbase + j2 * 16 * LDB + (kc + 1) * 32);
            }
#pragma unroll
            for (int j2 = 0; j2 < 4; ++j2) {
                mma16816s(acc[0][2 * j2],     af[cb][0], bf[cb][j2][0], bf[cb][j2][1]);
                mma16816s(acc[0][2 * j2 + 1], af[cb][0], bf[cb][j2][2], bf[cb][j2][3]);
                mma16816s(acc[1][2 * j2],     af[cb][1], bf[cb][j2][0], bf[cb][j2][1]);
                mma16816s(acc[1][2 * j2 + 1], af[cb][1], bf[cb][j2][2], bf[cb][j2][3]);
            }
        }

        // epilogue: running max + candidate append (index only)
#pragma unroll
        for (int f = 0; f < 2; ++f)
#pragma unroll
            for (int h = 0; h < 2; ++h) {
                float tm = -2.0f;
#pragma unroll
                for (int j = 0; j < 8; ++j)
                    tm = fmaxf(tm, fmaxf(acc[f][j][2 * h], acc[f][j][2 * h + 1]));
                tm = fmaxf(tm, __shfl_xor_sync(0xffffffffu, tm, 1));
                tm = fmaxf(tm, __shfl_xor_sync(0xffffffffu, tm, 2));
                float nm = fmaxf(rmax[f][h], tm);
                rmax[f][h] = nm;
                float thr = nm - MARGIN;
                int r = 32 * wy + 16 * f + 8 * h + g;
#pragma unroll
                for (int j = 0; j < 8; ++j)
#pragma unroll
                    for (int c = 0; c < 2; ++c) {
                        float v = acc[f][j][2 * h + c];
                        if (v >= thr) {
                            int pos = atomicAdd(&cnt[r], 1);
                            if (pos < CCAP) {
                                candI[r * CCAP + pos] =
                                    mt * 128 + wx * 64 + j * 8 + 2 * t + c;
                            }
                        }
                    }
            }
        __syncthreads();  // buf (cur) fully consumed before refill
    }

    // exact fp32 rescore of ALL appended candidates (R9-proven):
    // 2 threads per row; write g_idx.
    {
        int r = tid >> 1;
        int n = min(cnt[r], CCAP);
        float bv = -1e30f;
        int bi = 0x7fffffff;
        const float4* xa = (const float4*)(g_cn + ((size_t)b * NL + l0 + r) * ND);
        for (int e = (tid & 1); e < n; e += 2) {
            int m = candI[r * CCAP + e];
            const float4* xb = (const float4*)(g_en + ((size_t)b * NL + m) * ND);
            float s0 = 0, s1 = 0, s2 = 0, s3 = 0;
#pragma unroll
            for (int q = 0; q < 32; ++q) {
                float4 A = xa[q];
                float4 Bv = xb[q];
                s0 += A.x * Bv.x; s1 += A.y * Bv.y;
                s2 += A.z * Bv.z; s3 += A.w * Bv.w;
            }
            float s = (s0 + s1) + (s2 + s3);
            if (s > bv || (s == bv && m < bi)) { bv = s; bi = m; }
        }
        redV[tid] = bv;
        redI[tid] = bi;
        __syncthreads();
        if (tid < 128) {
            float v0 = redV[tid * 2], v1 = redV[tid * 2 + 1];
            int i0 = redI[tid * 2], i1 = redI[tid * 2 + 1];
            int best = (v1 > v0 || (v1 == v0 && i1 < i0)) ? i1 : i0;
            g_idx[b * NL + l0 + tid] = best;
        }
    }
}

// =================================================================
// Stage 4: finalize — out[t] = s_cn[t] + s_en[idx[t]] + 2*b2.
// =================================================================
__global__ void finalize_kernel(const float* __restrict__ b2,
                                float* __restrict__ out) {
    int tok = blockIdx.x * 256 + threadIdx.x;
    if (tok >= NB * NL) return;
    int base = tok & ~(NL - 1);
    out[tok] = g_scn[tok] + g_sen[base + g_idx[tok]] + 2.0f * b2[0];
}

// =================================================================
// launch — forked-stream overlap: smlp (FFMA) runs concurrently with
// simarg (tensor). Stream/events created once on the first
// (non-capture, correctness) call; reused in capture.
// =================================================================
extern "C" void kernel_launch(void* const* d_in, const int* in_sizes, int n_in,
                              void* d_out, int out_size) {
    const float* context = (const float*)d_in[0];
    const float* W1      = (const float*)d_in[1];
    const float* b1      = (const float*)d_in[2];
    const float* W2      = (const float*)d_in[3];
    const float* b2      = (const float*)d_in[4];
    float* out           = (float*)d_out;

    static cudaStream_t s1 = nullptr;
    static cudaEvent_t e1 = nullptr, e2 = nullptr;
    if (s1 == nullptr) {
        cudaStreamCreateWithFlags(&s1, cudaStreamNonBlocking);
        cudaEventCreateWithFlags(&e1, cudaEventDisableTiming);
        cudaEventCreateWithFlags(&e2, cudaEventDisableTiming);
        cudaFuncSetAttribute(smlp_kernel,
                             cudaFuncAttributeMaxDynamicSharedMemorySize,
                             SMLP_TOTAL);
        cudaFuncSetAttribute(simarg_kernel,
                             cudaFuncAttributeMaxDynamicSharedMemorySize,
                             SM_SIM_TOTAL);
    }

    // norm on the capture (default) stream
    {
        int warps = 2 * NB * NL;
        int threads = 256;
        int blocks = (warps * 32 + threads - 1) / threads;
        norm_kernel<<<blocks, threads>>>(context);
    }

    // fork: smlp on side stream
    cudaEventRecord(e1, 0);
    cudaStreamWaitEvent(s1, e1, 0);
    smlp_kernel<<<2 * NB * NL / 64, 128, SMLP_TOTAL, s1>>>(W1, b1, W2);

    // simarg on default stream (concurrent with smlp)
    {
        dim3 grid(NL / 128, NB);
        simarg_kernel<<<grid, 256, SM_SIM_TOTAL>>>();
    }

    // join + finalize
    cudaEventRecord(e2, s1);
    cudaStreamWaitEvent(0, e2, 0);
    finalize_kernel<<<(NB * NL + 255) / 256, 256>>>(b2, out);
}

// round 14
// speedup vs baseline: 1.0937x; 1.0937x over previous
#include <cuda_runtime.h>
#include <cuda_bf16.h>
#include <cstdint>

// Problem constants
#define NB 8
#define NL 2048
#define ND 128
#define EPSN 1e-8f
#define MARGIN 0.02f
#define CCAP 48

// ---------------- scratch (no allocation allowed) ----------------
__device__ __align__(128) float g_cn[NB * NL * ND];            // normalized ctx
__device__ __align__(128) float g_en[NB * NL * ND];            // normalized ent
__device__ __align__(128) __nv_bfloat16 g_cnbf[NB * NL * ND];  // bf16(cn)
__device__ __align__(128) __nv_bfloat16 g_enbf[NB * NL * ND];  // bf16(en)
__device__ __align__(128) int g_idx[NB * NL];

// ---------------- PTX helpers (compute_103-safe) ----------------
__device__ __forceinline__ uint32_t smem_u32(const void* p) {
    uint32_t a;
    asm("{ .reg .u64 t; cvta.to.shared.u64 t, %1; cvt.u32.u64 %0, t; }"
        : "=r"(a) : "l"(p));
    return a;
}
__device__ __forceinline__ void ldm4(uint32_t* a, uint32_t addr) {
    asm volatile("ldmatrix.sync.aligned.m8n8.x4.shared.b16 {%0,%1,%2,%3}, [%4];"
                 : "=r"(a[0]), "=r"(a[1]), "=r"(a[2]), "=r"(a[3]) : "r"(addr));
}
__device__ __forceinline__ void mma16816s(float* c, const uint32_t* a,
                                          uint32_t b0, uint32_t b1) {
    asm volatile(
        "mma.sync.aligned.m16n8k16.row.col.f32.bf16.bf16.f32 "
        "{%0,%1,%2,%3}, {%4,%5,%6,%7}, {%8,%9}, {%0,%1,%2,%3};"
        : "+f"(c[0]), "+f"(c[1]), "+f"(c[2]), "+f"(c[3])
        : "r"(a[0]), "r"(a[1]), "r"(a[2]), "r"(a[3]), "r"(b0), "r"(b1));
}
#define CP_ASYNC16(dst, src) \
    asm volatile("cp.async.cg.shared.global [%0], [%1], 16;" :: "r"(dst), "l"(src))
#define CP_COMMIT() asm volatile("cp.async.commit_group;")
#define CP_WAIT(n)  asm volatile("cp.async.wait_group %0;" :: "n"(n))

// =================================================================
// Stage 1: L2-normalize; 2 rows per warp (MLP=2 on the DRAM reads).
// Per-row arithmetic identical to the proven kernel -> bit-exact.
// =================================================================
__global__ void norm_kernel(const float* __restrict__ ctx) {
    int gwarp = (blockIdx.x * blockDim.x + threadIdx.x) >> 5;
    int lane  = threadIdx.x & 31;
    if (gwarp >= NB * NL) return;   // 16384 warps, 2 rows each

    int vr0 = 2 * gwarp;
    int vr1 = vr0 + 1;

    int wh0 = vr0 >> 14, rr0 = vr0 & 16383;
    int wh1 = vr1 >> 14, rr1 = vr1 & 16383;
    int b0 = rr0 >> 11, l0 = rr0 & 2047;
    int b1 = rr1 >> 11, l1 = rr1 & 2047;

    const float4* src0 =
        (const float4*)(ctx + ((size_t)(b0 * 2 + wh0) * NL + l0) * ND);
    const float4* src1 =
        (const float4*)(ctx + ((size_t)(b1 * 2 + wh1) * NL + l1) * ND);

    // issue both loads before any reduction (MLP=2)
    float4 v0 = src0[lane];
    float4 v1 = src1[lane];

    float s0 = v0.x * v0.x + v0.y * v0.y + v0.z * v0.z + v0.w * v0.w;
    float s1 = v1.x * v1.x + v1.y * v1.y + v1.z * v1.z + v1.w * v1.w;
#pragma unroll
    for (int o = 16; o; o >>= 1) {
        s0 += __shfl_xor_sync(0xffffffffu, s0, o);
        s1 += __shfl_xor_sync(0xffffffffu, s1, o);
    }
    float inv0 = 1.0f / fmaxf(sqrtf(s0), EPSN);
    float inv1 = 1.0f / fmaxf(sqrtf(s1), EPSN);

    float4 o0 = make_float4(v0.x * inv0, v0.y * inv0, v0.z * inv0, v0.w * inv0);
    float4 o1 = make_float4(v1.x * inv1, v1.y * inv1, v1.z * inv1, v1.w * inv1);

    ((float4*)((wh0 ? g_en : g_cn) + (size_t)rr0 * ND))[lane] = o0;
    ((float4*)((wh1 ? g_en : g_cn) + (size_t)rr1 * ND))[lane] = o1;

    {
        __nv_bfloat16* bd = (wh0 ? g_enbf : g_cnbf) + (size_t)rr0 * ND;
        __nv_bfloat162* hp = (__nv_bfloat162*)(bd + lane * 4);
        hp[0] = __halves2bfloat162(__float2bfloat16(o0.x), __float2bfloat16(o0.y));
        hp[1] = __halves2bfloat162(__float2bfloat16(o0.z), __float2bfloat16(o0.w));
    }
    {
        __nv_bfloat16* bd = (wh1 ? g_enbf : g_cnbf) + (size_t)rr1 * ND;
        __nv_bfloat162* hp = (__nv_bfloat162*)(bd + lane * 4);
        hp[0] = __halves2bfloat162(__float2bfloat16(o1.x), __float2bfloat16(o1.y));
        hp[1] = __halves2bfloat162(__float2bfloat16(o1.z), __float2bfloat16(o1.w));
    }
}

// =================================================================
// Stage 2: HMMA sim-GEMM + fused argmax -> g_idx.
// R11 VERBATIM (passed, 132.16 total): R8 3-stage cp.async shell,
// x4 B-loads + fragment pipeline, candidate filter + exact rescore.
// =================================================================
#define LDB 272
#define SM_AT   0                           // 34816
#define SM_BT0  34816                       // 3 buffers x 34816
#define SM_CS   139264                      // 128*48*4 = 24576
#define SM_CI   163840                      // 24576
#define SM_CNT  188416                      // 512
#define SM_HM   188928                      // 1024
#define SM_SIM_TOTAL 189952

__global__ __launch_bounds__(256, 1) void simarg_kernel() {
    extern __shared__ char smc[];
    float* candV = (float*)(smc + SM_CS);
    int*   candI = (int*)(smc + SM_CI);
    int*   cnt   = (int*)(smc + SM_CNT);
    float* hmax  = (float*)(smc + SM_HM);

    int tid = threadIdx.x, w = tid >> 5, lane = tid & 31;
    int wy = w >> 1, wx = w & 1;
    int g = lane >> 2, t = lane & 3;
    int b = blockIdx.y, l0 = blockIdx.x * 128;

    if (tid < 128) cnt[tid] = 0;

    const uint4* asrc = (const uint4*)(g_cnbf + ((size_t)b * NL + l0) * ND);
#pragma unroll
    for (int i = tid; i < 2048; i += 256) {
        int row = i >> 4, c = i & 15;
        *(uint4*)(smc + SM_AT + row * LDB + c * 16) = asrc[row * 16 + c];
    }

    const char* esrc = (const char*)(g_enbf + (size_t)b * NL * ND);
    uint32_t sb = smem_u32(smc);

#pragma unroll
    for (int q = 0; q < 2; ++q) {
#pragma unroll
        for (int i = tid; i < 2048; i += 256) {
            int row = i >> 4, c = i & 15;
            CP_ASYNC16(sb + SM_BT0 + q * 34816 + row * LDB + c * 16,
                       esrc + ((size_t)q * 128 + row) * 256 + c * 16);
        }
        CP_COMMIT();
    }

    uint32_t aaddr = sb + SM_AT + ((32 * wy + (lane & 15)) * LDB + (lane >> 4) * 16);
    uint32_t boff = (lane & 7) * LDB + ((lane >> 3) & 1) * 16 + (lane >> 4) * 8 * LDB;

    float rmax[2][2] = {{-2.0f, -2.0f}, {-2.0f, -2.0f}};

    for (int mt = 0; mt < 16; ++mt) {
        if (mt < 15) { CP_WAIT(1); } else { CP_WAIT(0); }
        __syncthreads();

        uint32_t bbase = sb + SM_BT0 + (mt % 3) * 34816 + boff + wx * 64 * LDB;

        float acc[2][8][4];
#pragma unroll
        for (int f = 0; f < 2; ++f)
#pragma unroll
            for (int j = 0; j < 8; ++j)
#pragma unroll
                for (int c = 0; c < 4; ++c) acc[f][j][c] = 0.0f;

        uint32_t af[2][2][4];
        uint32_t bf[2][4][4];
        ldm4(af[0][0], aaddr);
        ldm4(af[0][1], aaddr + 16 * LDB);
#pragma unroll
        for (int j2 = 0; j2 < 4; ++j2) ldm4(bf[0][j2], bbase + j2 * 16 * LDB);

#pragma unroll
        for (int kc = 0; kc < 8; ++kc) {
            int cb = kc & 1, nx = cb ^ 1;
            if (kc < 7) {
                ldm4(af[nx][0], aaddr + (kc + 1) * 32);
                ldm4(af[nx][1], aaddr + 16 * LDB + (kc + 1) * 32);
#pragma unroll
                for (int j2 = 0; j2 < 4; ++j2)
                    ldm4(bf[nx][j2], bbase + j2 * 16 * LDB + (kc + 1) * 32);
            }
#pragma unroll
            for (int j2 = 0; j2 < 4; ++j2) {
                mma16816s(acc[0][2 * j2],     af[cb][0], bf[cb][j2][0], bf[cb][j2][1]);
                mma16816s(acc[0][2 * j2 + 1], af[cb][0], bf[cb][j2][2], bf[cb][j2][3]);
                mma16816s(acc[1][2 * j2],     af[cb][1], bf[cb][j2][0], bf[cb][j2][1]);
                mma16816s(acc[1][2 * j2 + 1], af[cb][1], bf[cb][j2][2], bf[cb][j2][3]);
            }
        }

#pragma unroll
        for (int f = 0; f < 2; ++f)
#pragma unroll
            for (int h = 0; h < 2; ++h) {
                float tm = -2.0f;
#pragma unroll
                for (int j = 0; j < 8; ++j)
                    tm = fmaxf(tm, fmaxf(acc[f][j][2 * h], acc[f][j][2 * h + 1]));
                tm = fmaxf(tm, __shfl_xor_sync(0xffffffffu, tm, 1));
                tm = fmaxf(tm, __shfl_xor_sync(0xffffffffu, tm, 2));
                float nm = fmaxf(rmax[f][h], tm);
                rmax[f][h] = nm;
                float thr = nm - MARGIN;
                int r = 32 * wy + 16 * f + 8 * h + g;
#pragma unroll
                for (int j = 0; j < 8; ++j)
#pragma unroll
                    for (int c = 0; c < 2; ++c) {
                        float v = acc[f][j][2 * h + c];
                        if (v >= thr) {
                            int pos = atomicAdd(&cnt[r], 1);
                            if (pos < CCAP) {
                                candV[r * CCAP + pos] = v;
                                candI[r * CCAP + pos] =
                                    mt * 128 + wx * 64 + j * 8 + 2 * t + c;
                            }
                        }
                    }
            }
        __syncthreads();

        if (mt + 2 < 16) {
            int nb_ = SM_BT0 + ((mt + 2) % 3) * 34816;
#pragma unroll
            for (int i = tid; i < 2048; i += 256) {
                int row = i >> 4, c = i & 15;
                CP_ASYNC16(sb + nb_ + row * LDB + c * 16,
                           esrc + ((size_t)(mt + 2) * 128 + row) * 256 + c * 16);
            }
            CP_COMMIT();
        }
    }

    if (t == 0) {
#pragma unroll
        for (int f = 0; f < 2; ++f)
#pragma unroll
            for (int h = 0; h < 2; ++h)
                hmax[(32 * wy + 16 * f + 8 * h + g) * 2 + wx] = rmax[f][h];
    }
    __syncthreads();

    {
        int r = tid >> 1;
        float Mb = fmaxf(hmax[r * 2], hmax[r * 2 + 1]);
        float thr = Mb - MARGIN;
        int n = min(cnt[r], CCAP);
        float bv = -1e30f;
        int bi = 0x7fffffff;
        const float4* xa = (const float4*)(g_cn + ((size_t)b * NL + l0 + r) * ND);
        for (int e = (tid & 1); e < n; e += 2) {
            if (candV[r * CCAP + e] < thr) continue;
            int m = candI[r * CCAP + e];
            const float4* xb = (const float4*)(g_en + ((size_t)b * NL + m) * ND);
            float s0 = 0, s1 = 0, s2 = 0, s3 = 0;
#pragma unroll
            for (int q = 0; q < 32; ++q) {
                float4 A = xa[q];
                float4 Bv = xb[q];
                s0 += A.x * Bv.x; s1 += A.y * Bv.y;
                s2 += A.z * Bv.z; s3 += A.w * Bv.w;
            }
            float s = (s0 + s1) + (s2 + s3);
            if (s > bv || (s == bv && m < bi)) { bv = s; bi = m; }
        }
        __syncthreads();
        candV[tid] = bv;
        candI[tid] = bi;
        __syncthreads();
        if (tid < 128) {
            float v0 = candV[tid * 2], v1 = candV[tid * 2 + 1];
            int i0 = candI[tid * 2], i1 = candI[tid * 2 + 1];
            int best = (v1 > v0 || (v1 == v0 && i1 < i0)) ? i1 : i0;
            g_idx[b * NL + l0 + tid] = best;
        }
    }
}

// =================================================================
// Stage 3: per-token 2-row MLP + reduction (R3 verbatim; min-blocks
// hint for 2-CTA/SM co-residency).
// =================================================================
#define W1S 132

__global__ __launch_bounds__(128, 2) void mlp_kernel(
    const float* __restrict__ W1, const float* __restrict__ b1,
    const float* __restrict__ W2, const float* __restrict__ b2,
    float* __restrict__ out) {
    extern __shared__ float sm[];
    float* W1t  = sm;
    float* rows = sm + 128 * W1S;
    float* part = sm + 128 * W1S + 16 * 128;

    int tid  = threadIdx.x;
    int lane = tid & 31;
    int wp   = tid >> 5;

#pragma unroll
    for (int i = 0; i < 128; ++i) {
        int flat = i * 128 + tid;
        int j = flat & 127, k = flat >> 7;
        W1t[j * W1S + k] = W1[k * 128 + j];
    }
    float bias = b1[tid];
    float w2   = W2[tid];
    float bb2  = b2[0];

    int tok0 = blockIdx.x * 64;
    for (int g0 = 0; g0 < 64; g0 += 8) {
        __syncthreads();
#pragma unroll
        for (int i = 0; i < 16; ++i) {
            int flat = i * 128 + tid;
            int r = flat >> 7, k = flat & 127;
            int tok = tok0 + g0 + (r >> 1);
            const float* src;
            if (r & 1) {
                int bb = tok >> 11;
                int mi = g_idx[tok];
                src = g_en + ((size_t)(bb << 11) + mi) * ND;
            } else {
                src = g_cn + (size_t)tok * ND;
            }
            rows[r * 128 + k] = src[k];
        }
        __syncthreads();

        float acc[16];
#pragma unroll
        for (int r = 0; r < 16; ++r) acc[r] = bias;

#pragma unroll 4
        for (int kq = 0; kq < 32; ++kq) {
            float4 w4 = *(const float4*)(W1t + tid * W1S + kq * 4);
#pragma unroll
            for (int r = 0; r < 16; ++r) {
                float4 x = *(const float4*)(rows + r * 128 + kq * 4);
                acc[r] += w4.x * x.x + w4.y * x.y + w4.z * x.z + w4.w * x.w;
            }
        }

        float c[8];
#pragma unroll
        for (int g = 0; g < 8; ++g) {
            float h0 = fmaxf(acc[2 * g], 0.0f);
            float h1 = fmaxf(acc[2 * g + 1], 0.0f);
            c[g] = (h0 + h1) * w2;
        }
#pragma unroll
        for (int g = 0; g < 8; ++g) {
            float v = c[g];
#pragma unroll
            for (int o = 16; o; o >>= 1) v += __shfl_xor_sync(0xffffffffu, v, o);
            c[g] = v;
        }
        if (lane == 0) {
#pragma unroll
            for (int g = 0; g < 8; ++g) part[g * 4 + wp] = c[g];
        }
        __syncthreads();
        if (tid < 8) {
            float s = part[tid * 4] + part[tid * 4 + 1] +
                      part[tid * 4 + 2] + part[tid * 4 + 3];
            out[tok0 + g0 + tid] = s + 2.0f * bb2;
        }
    }
}

// =================================================================
// launch
// =================================================================
extern "C" void kernel_launch(void* const* d_in, const int* in_sizes, int n_in,
                              void* d_out, int out_size) {
    const float* context = (const float*)d_in[0];
    const float* W1      = (const float*)d_in[1];
    const float* b1      = (const float*)d_in[2];
    const float* W2      = (const float*)d_in[3];
    const float* b2      = (const float*)d_in[4];
    float* out           = (float*)d_out;

    {
        // 16384 warps, 2 rows each
        int warps = NB * NL;
        int threads = 256;
        int blocks = (warps * 32 + threads - 1) / threads;  // 2048
        norm_kernel<<<blocks, threads>>>(context);
    }
    {
        cudaFuncSetAttribute(simarg_kernel,
                             cudaFuncAttributeMaxDynamicSharedMemorySize,
                             SM_SIM_TOTAL);
        dim3 grid(NL / 128, NB);
        simarg_kernel<<<grid, 256, SM_SIM_TOTAL>>>();
    }
    {
        size_t smem = (size_t)(128 * W1S + 16 * 128 + 64) * sizeof(float);
        cudaFuncSetAttribute(mlp_kernel,
                             cudaFuncAttributeMaxDynamicSharedMemorySize,
                             (int)smem);
        mlp_kernel<<<NB * NL / 64, 128, smem>>>(W1, b1, W2, b2, out);
    }
}

// round 15
// speedup vs baseline: 1.3186x; 1.2056x over previous
#include <cuda_runtime.h>
#include <cuda_bf16.h>
#include <cstdint>

// Problem constants
#define NB 8
#define NL 2048
#define ND 128
#define EPSN 1e-8f
#define MARGIN 0.02f
#define CCAP 48

// ---------------- scratch (no allocation allowed) ----------------
__device__ __align__(128) float g_cn[NB * NL * ND];            // normalized ctx
__device__ __align__(128) float g_en[NB * NL * ND];            // normalized ent
__device__ __align__(128) __nv_bfloat16 g_cnbf[NB * NL * ND];  // bf16(cn)
__device__ __align__(128) __nv_bfloat16 g_enbf[NB * NL * ND];  // bf16(en)
__device__ __align__(128) float g_scn[NB * NL];                // s(cn row)
__device__ __align__(128) float g_sen[NB * NL];                // s(en row)

// ---------------- PTX helpers (compute_103-safe) ----------------
__device__ __forceinline__ uint32_t smem_u32(const void* p) {
    uint32_t a;
    asm("{ .reg .u64 t; cvta.to.shared.u64 t, %1; cvt.u32.u64 %0, t; }"
        : "=r"(a) : "l"(p));
    return a;
}
__device__ __forceinline__ void ldm4(uint32_t* a, uint32_t addr) {
    asm volatile("ldmatrix.sync.aligned.m8n8.x4.shared.b16 {%0,%1,%2,%3}, [%4];"
                 : "=r"(a[0]), "=r"(a[1]), "=r"(a[2]), "=r"(a[3]) : "r"(addr));
}
__device__ __forceinline__ void mma16816s(float* c, const uint32_t* a,
                                          uint32_t b0, uint32_t b1) {
    asm volatile(
        "mma.sync.aligned.m16n8k16.row.col.f32.bf16.bf16.f32 "
        "{%0,%1,%2,%3}, {%4,%5,%6,%7}, {%8,%9}, {%0,%1,%2,%3};"
        : "+f"(c[0]), "+f"(c[1]), "+f"(c[2]), "+f"(c[3])
        : "r"(a[0]), "r"(a[1]), "r"(a[2]), "r"(a[3]), "r"(b0), "r"(b1));
}
#define CP_ASYNC16(dst, src) \
    asm volatile("cp.async.cg.shared.global [%0], [%1], 16;" :: "r"(dst), "l"(src))
#define CP_COMMIT() asm volatile("cp.async.commit_group;")
#define CP_WAIT(n)  asm volatile("cp.async.wait_group %0;" :: "n"(n))

// =================================================================
// Stage 1: L2-normalize; 2 rows per warp (R14 verbatim, 9.1us).
// =================================================================
__global__ void norm_kernel(const float* __restrict__ ctx) {
    int gwarp = (blockIdx.x * blockDim.x + threadIdx.x) >> 5;
    int lane  = threadIdx.x & 31;
    if (gwarp >= NB * NL) return;

    int vr0 = 2 * gwarp;
    int vr1 = vr0 + 1;
    int wh0 = vr0 >> 14, rr0 = vr0 & 16383;
    int wh1 = vr1 >> 14, rr1 = vr1 & 16383;
    int b0 = rr0 >> 11, l0 = rr0 & 2047;
    int b1_ = rr1 >> 11, l1 = rr1 & 2047;

    const float4* src0 =
        (const float4*)(ctx + ((size_t)(b0 * 2 + wh0) * NL + l0) * ND);
    const float4* src1 =
        (const float4*)(ctx + ((size_t)(b1_ * 2 + wh1) * NL + l1) * ND);
    float4 v0 = src0[lane];
    float4 v1 = src1[lane];

    float s0 = v0.x * v0.x + v0.y * v0.y + v0.z * v0.z + v0.w * v0.w;
    float s1 = v1.x * v1.x + v1.y * v1.y + v1.z * v1.z + v1.w * v1.w;
#pragma unroll
    for (int o = 16; o; o >>= 1) {
        s0 += __shfl_xor_sync(0xffffffffu, s0, o);
        s1 += __shfl_xor_sync(0xffffffffu, s1, o);
    }
    float inv0 = 1.0f / fmaxf(sqrtf(s0), EPSN);
    float inv1 = 1.0f / fmaxf(sqrtf(s1), EPSN);
    float4 o0 = make_float4(v0.x * inv0, v0.y * inv0, v0.z * inv0, v0.w * inv0);
    float4 o1 = make_float4(v1.x * inv1, v1.y * inv1, v1.z * inv1, v1.w * inv1);

    ((float4*)((wh0 ? g_en : g_cn) + (size_t)rr0 * ND))[lane] = o0;
    ((float4*)((wh1 ? g_en : g_cn) + (size_t)rr1 * ND))[lane] = o1;
    {
        __nv_bfloat16* bd = (wh0 ? g_enbf : g_cnbf) + (size_t)rr0 * ND;
        __nv_bfloat162* hp = (__nv_bfloat162*)(bd + lane * 4);
        hp[0] = __halves2bfloat162(__float2bfloat16(o0.x), __float2bfloat16(o0.y));
        hp[1] = __halves2bfloat162(__float2bfloat16(o0.z), __float2bfloat16(o0.w));
    }
    {
        __nv_bfloat16* bd = (wh1 ? g_enbf : g_cnbf) + (size_t)rr1 * ND;
        __nv_bfloat162* hp = (__nv_bfloat162*)(bd + lane * 4);
        hp[0] = __halves2bfloat162(__float2bfloat16(o1.x), __float2bfloat16(o1.y));
        hp[1] = __halves2bfloat162(__float2bfloat16(o1.z), __float2bfloat16(o1.w));
    }
}

// =================================================================
// Stage 2: tensor-core per-row MLP scalar via 3-term split-bf16:
//   s(row) = relu(row.W1 + b1) @ W2
//   row.W1 ~= hi.Whi + hi.Wlo + lo.Whi   (fp32 accum; drops lo.Wlo)
// CTA: 128 rows, 256 threads, 8 warps (wy=m-slot of 32, wx=n-slot
// of 64). ldmatrix/MMA addressing identical to the proven R11 GEMM;
// epilogue C-fragment mapping identical to the proven R3 epilogue.
// =================================================================
#define LDB 272
#define TC_AHI 0
#define TC_ALO 34816
#define TC_BHI 69632
#define TC_BLO 104448
#define TC_B1  139264
#define TC_W2  139776
#define TC_RED 140288
#define TC_TOTAL 141312

__global__ __launch_bounds__(256, 1) void smlp_tc_kernel(
    const float* __restrict__ W1, const float* __restrict__ b1,
    const float* __restrict__ W2) {
    extern __shared__ char smc[];
    float* b1s = (float*)(smc + TC_B1);
    float* w2s = (float*)(smc + TC_W2);
    float* red = (float*)(smc + TC_RED);

    int tid = threadIdx.x, w = tid >> 5, lane = tid & 31;
    int wy = w >> 1, wx = w & 1;
    int g = lane >> 2, t = lane & 3;

    int vr0 = blockIdx.x * 128;
    const float* rowsrc = (vr0 < NB * NL)
        ? g_cn + (size_t)vr0 * ND
        : g_en + (size_t)(vr0 - NB * NL) * ND;

    // --- stage W1 transposed hi/lo: Bt[n][k] = W1[k][n] ---
    for (int i = tid; i < 16384; i += 256) {
        int k = i >> 7, n = i & 127;
        float x = W1[k * 128 + n];
        __nv_bfloat16 hi = __float2bfloat16(x);
        __nv_bfloat16 lo = __float2bfloat16(x - __bfloat162float(hi));
        *(__nv_bfloat16*)(smc + TC_BHI + n * LDB + k * 2) = hi;
        *(__nv_bfloat16*)(smc + TC_BLO + n * LDB + k * 2) = lo;
    }
    // --- stage A rows hi/lo ---
    for (int i = tid; i < 16384; i += 256) {
        int r = i >> 7, k = i & 127;
        float x = rowsrc[(size_t)r * ND + k];
        __nv_bfloat16 hi = __float2bfloat16(x);
        __nv_bfloat16 lo = __float2bfloat16(x - __bfloat162float(hi));
        *(__nv_bfloat16*)(smc + TC_AHI + r * LDB + k * 2) = hi;
        *(__nv_bfloat16*)(smc + TC_ALO + r * LDB + k * 2) = lo;
    }
    if (tid < 128) { b1s[tid] = b1[tid]; w2s[tid] = W2[tid]; }
    __syncthreads();

    uint32_t sb = smem_u32(smc);
    // A base: rows 32*wy + (lane&15), k-half via lane>>4 (R11 pattern)
    uint32_t aoff = (32 * wy + (lane & 15)) * LDB + (lane >> 4) * 16;
    // B base: 2 n-blocks per ldm4 (R11 pattern), warp covers 64 cols
    uint32_t boff = (lane & 7) * LDB + ((lane >> 3) & 1) * 16 +
                    (lane >> 4) * 8 * LDB + wx * 64 * LDB;

    float acc[2][8][4];
#pragma unroll
    for (int f = 0; f < 2; ++f)
#pragma unroll
        for (int j = 0; j < 8; ++j)
#pragma unroll
            for (int c = 0; c < 4; ++c) acc[f][j][c] = 0.0f;

#pragma unroll
    for (int kc = 0; kc < 8; ++kc) {
        uint32_t ahi0[4], ahi1[4], alo0[4], alo1[4];
        ldm4(ahi0, sb + TC_AHI + aoff + kc * 32);
        ldm4(ahi1, sb + TC_AHI + aoff + 16 * LDB + kc * 32);
        ldm4(alo0, sb + TC_ALO + aoff + kc * 32);
        ldm4(alo1, sb + TC_ALO + aoff + 16 * LDB + kc * 32);
#pragma unroll
        for (int j2 = 0; j2 < 4; ++j2) {
            uint32_t bh[4], bl[4];
            ldm4(bh, sb + TC_BHI + boff + j2 * 16 * LDB + kc * 32);
            ldm4(bl, sb + TC_BLO + boff + j2 * 16 * LDB + kc * 32);
            // term hi.Whi
            mma16816s(acc[0][2 * j2],     ahi0, bh[0], bh[1]);
            mma16816s(acc[0][2 * j2 + 1], ahi0, bh[2], bh[3]);
            mma16816s(acc[1][2 * j2],     ahi1, bh[0], bh[1]);
            mma16816s(acc[1][2 * j2 + 1], ahi1, bh[2], bh[3]);
            // term hi.Wlo
            mma16816s(acc[0][2 * j2],     ahi0, bl[0], bl[1]);
            mma16816s(acc[0][2 * j2 + 1], ahi0, bl[2], bl[3]);
            mma16816s(acc[1][2 * j2],     ahi1, bl[0], bl[1]);
            mma16816s(acc[1][2 * j2 + 1], ahi1, bl[2], bl[3]);
            // term lo.Whi
            mma16816s(acc[0][2 * j2],     alo0, bh[0], bh[1]);
            mma16816s(acc[0][2 * j2 + 1], alo0, bh[2], bh[3]);
            mma16816s(acc[1][2 * j2],     alo1, bh[0], bh[1]);
            mma16816s(acc[1][2 * j2 + 1], alo1, bh[2], bh[3]);
        }
    }

    // epilogue: h = acc + b1; relu; dot W2; reduce.
    // C-fragment mapping (R3-proven): row = 32wy+16f+8h+g,
    // col = wx*64 + j*8 + 2t + c.
    float b1r[16], w2r[16];
#pragma unroll
    for (int j = 0; j < 8; ++j)
#pragma unroll
        for (int c = 0; c < 2; ++c) {
            int col = wx * 64 + j * 8 + 2 * t + c;
            b1r[j * 2 + c] = b1s[col];
            w2r[j * 2 + c] = w2s[col];
        }

#pragma unroll
    for (int f = 0; f < 2; ++f)
#pragma unroll
        for (int h = 0; h < 2; ++h) {
            float p = 0.0f;
#pragma unroll
            for (int j = 0; j < 8; ++j)
#pragma unroll
                for (int c = 0; c < 2; ++c) {
                    float v = acc[f][j][2 * h + c] + b1r[j * 2 + c];
                    p += fmaxf(v, 0.0f) * w2r[j * 2 + c];
                }
            p += __shfl_xor_sync(0xffffffffu, p, 1);
            p += __shfl_xor_sync(0xffffffffu, p, 2);
            if (t == 0) red[(32 * wy + 16 * f + 8 * h + g) * 2 + wx] = p;
        }
    __syncthreads();
    if (tid < 128) {
        float s = red[tid * 2] + red[tid * 2 + 1];
        int vr = vr0 + tid;
        if (vr < NB * NL) g_scn[vr] = s;
        else              g_sen[vr - NB * NL] = s;
    }
}

// =================================================================
// Stage 3: HMMA sim-GEMM + fused argmax; R14 body verbatim with the
// R8-proven direct-output ending (g_scn/g_sen + b2 -> out).
// =================================================================
#define SM_AT   0                           // 34816
#define SM_BT0  34816                       // 3 buffers x 34816
#define SM_CS   139264                      // 128*48*4 = 24576
#define SM_CI   163840                      // 24576
#define SM_CNT  188416                      // 512
#define SM_HM   188928                      // 1024
#define SM_SIM_TOTAL 189952

__global__ __launch_bounds__(256, 1) void simarg_kernel(
    const float* __restrict__ b2, float* __restrict__ out) {
    extern __shared__ char smc[];
    float* candV = (float*)(smc + SM_CS);
    int*   candI = (int*)(smc + SM_CI);
    int*   cnt   = (int*)(smc + SM_CNT);
    float* hmax  = (float*)(smc + SM_HM);

    int tid = threadIdx.x, w = tid >> 5, lane = tid & 31;
    int wy = w >> 1, wx = w & 1;
    int g = lane >> 2, t = lane & 3;
    int b = blockIdx.y, l0 = blockIdx.x * 128;

    if (tid < 128) cnt[tid] = 0;

    const uint4* asrc = (const uint4*)(g_cnbf + ((size_t)b * NL + l0) * ND);
#pragma unroll
    for (int i = tid; i < 2048; i += 256) {
        int row = i >> 4, c = i & 15;
        *(uint4*)(smc + SM_AT + row * LDB + c * 16) = asrc[row * 16 + c];
    }

    const char* esrc = (const char*)(g_enbf + (size_t)b * NL * ND);
    uint32_t sb = smem_u32(smc);

#pragma unroll
    for (int q = 0; q < 2; ++q) {
#pragma unroll
        for (int i = tid; i < 2048; i += 256) {
            int row = i >> 4, c = i & 15;
            CP_ASYNC16(sb + SM_BT0 + q * 34816 + row * LDB + c * 16,
                       esrc + ((size_t)q * 128 + row) * 256 + c * 16);
        }
        CP_COMMIT();
    }

    uint32_t aaddr = sb + SM_AT + ((32 * wy + (lane & 15)) * LDB + (lane >> 4) * 16);
    uint32_t boff = (lane & 7) * LDB + ((lane >> 3) & 1) * 16 + (lane >> 4) * 8 * LDB;

    float rmax[2][2] = {{-2.0f, -2.0f}, {-2.0f, -2.0f}};

    for (int mt = 0; mt < 16; ++mt) {
        if (mt < 15) { CP_WAIT(1); } else { CP_WAIT(0); }
        __syncthreads();

        uint32_t bbase = sb + SM_BT0 + (mt % 3) * 34816 + boff + wx * 64 * LDB;

        float acc[2][8][4];
#pragma unroll
        for (int f = 0; f < 2; ++f)
#pragma unroll
            for (int j = 0; j < 8; ++j)
#pragma unroll
                for (int c = 0; c < 4; ++c) acc[f][j][c] = 0.0f;

        uint32_t af[2][2][4];
        uint32_t bf[2][4][4];
        ldm4(af[0][0], aaddr);
        ldm4(af[0][1], aaddr + 16 * LDB);
#pragma unroll
        for (int j2 = 0; j2 < 4; ++j2) ldm4(bf[0][j2], bbase + j2 * 16 * LDB);

#pragma unroll
        for (int kc = 0; kc < 8; ++kc) {
            int cb = kc & 1, nx = cb ^ 1;
            if (kc < 7) {
                ldm4(af[nx][0], aaddr + (kc + 1) * 32);
                ldm4(af[nx][1], aaddr + 16 * LDB + (kc + 1) * 32);
#pragma unroll
                for (int j2 = 0; j2 < 4; ++j2)
                    ldm4(bf[nx][j2], bbase + j2 * 16 * LDB + (kc + 1) * 32);
            }
#pragma unroll
            for (int j2 = 0; j2 < 4; ++j2) {
                mma16816s(acc[0][2 * j2],     af[cb][0], bf[cb][j2][0], bf[cb][j2][1]);
                mma16816s(acc[0][2 * j2 + 1], af[cb][0], bf[cb][j2][2], bf[cb][j2][3]);
                mma16816s(acc[1][2 * j2],     af[cb][1], bf[cb][j2][0], bf[cb][j2][1]);
                mma16816s(acc[1][2 * j2 + 1], af[cb][1], bf[cb][j2][2], bf[cb][j2][3]);
            }
        }

#pragma unroll
        for (int f = 0; f < 2; ++f)
#pragma unroll
            for (int h = 0; h < 2; ++h) {
                float tm = -2.0f;
#pragma unroll
                for (int j = 0; j < 8; ++j)
                    tm = fmaxf(tm, fmaxf(acc[f][j][2 * h], acc[f][j][2 * h + 1]));
                tm = fmaxf(tm, __shfl_xor_sync(0xffffffffu, tm, 1));
                tm = fmaxf(tm, __shfl_xor_sync(0xffffffffu, tm, 2));
                float nm = fmaxf(rmax[f][h], tm);
                rmax[f][h] = nm;
                float thr = nm - MARGIN;
                int r = 32 * wy + 16 * f + 8 * h + g;
#pragma unroll
                for (int j = 0; j < 8; ++j)
#pragma unroll
                    for (int c = 0; c < 2; ++c) {
                        float v = acc[f][j][2 * h + c];
                        if (v >= thr) {
                            int pos = atomicAdd(&cnt[r], 1);
                            if (pos < CCAP) {
                                candV[r * CCAP + pos] = v;
                                candI[r * CCAP + pos] =
                                    mt * 128 + wx * 64 + j * 8 + 2 * t + c;
                            }
                        }
                    }
            }
        __syncthreads();

        if (mt + 2 < 16) {
            int nb_ = SM_BT0 + ((mt + 2) % 3) * 34816;
#pragma unroll
            for (int i = tid; i < 2048; i += 256) {
                int row = i >> 4, c = i & 15;
                CP_ASYNC16(sb + nb_ + row * LDB + c * 16,
                           esrc + ((size_t)(mt + 2) * 128 + row) * 256 + c * 16);
            }
            CP_COMMIT();
        }
    }

    if (t == 0) {
#pragma unroll
        for (int f = 0; f < 2; ++f)
#pragma unroll
            for (int h = 0; h < 2; ++h)
                hmax[(32 * wy + 16 * f + 8 * h + g) * 2 + wx] = rmax[f][h];
    }
    __syncthreads();

    {
        int r = tid >> 1;
        float Mb = fmaxf(hmax[r * 2], hmax[r * 2 + 1]);
        float thr = Mb - MARGIN;
        int n = min(cnt[r], CCAP);
        float bv = -1e30f;
        int bi = 0x7fffffff;
        const float4* xa = (const float4*)(g_cn + ((size_t)b * NL + l0 + r) * ND);
        for (int e = (tid & 1); e < n; e += 2) {
            if (candV[r * CCAP + e] < thr) continue;
            int m = candI[r * CCAP + e];
            const float4* xb = (const float4*)(g_en + ((size_t)b * NL + m) * ND);
            float s0 = 0, s1 = 0, s2 = 0, s3 = 0;
#pragma unroll
            for (int q = 0; q < 32; ++q) {
                float4 A = xa[q];
                float4 Bv = xb[q];
                s0 += A.x * Bv.x; s1 += A.y * Bv.y;
                s2 += A.z * Bv.z; s3 += A.w * Bv.w;
            }
            float s = (s0 + s1) + (s2 + s3);
            if (s > bv || (s == bv && m < bi)) { bv = s; bi = m; }
        }
        __syncthreads();
        candV[tid] = bv;
        candI[tid] = bi;
        __syncthreads();
        if (tid < 128) {
            float v0 = candV[tid * 2], v1 = candV[tid * 2 + 1];
            int i0 = candI[tid * 2], i1 = candI[tid * 2 + 1];
            int best = (v1 > v0 || (v1 == v0 && i1 < i0)) ? i1 : i0;
            float bb2 = b2[0];
            out[b * NL + l0 + tid] = g_scn[b * NL + l0 + tid] +
                                     g_sen[b * NL + best] + 2.0f * bb2;
        }
    }
}

// =================================================================
// launch
// =================================================================
extern "C" void kernel_launch(void* const* d_in, const int* in_sizes, int n_in,
                              void* d_out, int out_size) {
    const float* context = (const float*)d_in[0];
    const float* W1      = (const float*)d_in[1];
    const float* b1      = (const float*)d_in[2];
    const float* W2      = (const float*)d_in[3];
    const float* b2      = (const float*)d_in[4];
    float* out           = (float*)d_out;

    {
        int warps = NB * NL;  // 2 rows per warp
        int threads = 256;
        int blocks = (warps * 32 + threads - 1) / threads;
        norm_kernel<<<blocks, threads>>>(context);
    }
    {
        cudaFuncSetAttribute(smlp_tc_kernel,
                             cudaFuncAttributeMaxDynamicSharedMemorySize,
                             TC_TOTAL);
        smlp_tc_kernel<<<2 * NB * NL / 128, 256, TC_TOTAL>>>(W1, b1, W2);
    }
    {
        cudaFuncSetAttribute(simarg_kernel,
                             cudaFuncAttributeMaxDynamicSharedMemorySize,
                             SM_SIM_TOTAL);
        dim3 grid(NL / 128, NB);
        simarg_kernel<<<grid, 256, SM_SIM_TOTAL>>>(b2, out);
    }
}

// round 16
// speedup vs baseline: 1.4821x; 1.1240x over previous
#include <cuda_runtime.h>
#include <cuda_bf16.h>
#include <cstdint>

// Problem constants
#define NB 8
#define NL 2048
#define ND 128
#define EPSN 1e-8f
#define MARGIN 0.02f
#define CCAP 48

// ---------------- scratch (no allocation allowed) ----------------
__device__ __align__(128) float g_cn[NB * NL * ND];            // normalized ctx
__device__ __align__(128) float g_en[NB * NL * ND];            // normalized ent
__device__ __align__(128) __nv_bfloat16 g_cnbf[NB * NL * ND];  // bf16(cn)
__device__ __align__(128) __nv_bfloat16 g_enbf[NB * NL * ND];  // bf16(en)
__device__ __align__(128) float g_scn[NB * NL];                // s(cn row)
__device__ __align__(128) float g_sen[NB * NL];                // s(en row)

// ---------------- PTX helpers (compute_103-safe) ----------------
__device__ __forceinline__ uint32_t smem_u32(const void* p) {
    uint32_t a;
    asm("{ .reg .u64 t; cvta.to.shared.u64 t, %1; cvt.u32.u64 %0, t; }"
        : "=r"(a) : "l"(p));
    return a;
}
__device__ __forceinline__ void ldm4(uint32_t* a, uint32_t addr) {
    asm volatile("ldmatrix.sync.aligned.m8n8.x4.shared.b16 {%0,%1,%2,%3}, [%4];"
                 : "=r"(a[0]), "=r"(a[1]), "=r"(a[2]), "=r"(a[3]) : "r"(addr));
}
__device__ __forceinline__ void mma16816s(float* c, const uint32_t* a,
                                          uint32_t b0, uint32_t b1) {
    asm volatile(
        "mma.sync.aligned.m16n8k16.row.col.f32.bf16.bf16.f32 "
        "{%0,%1,%2,%3}, {%4,%5,%6,%7}, {%8,%9}, {%0,%1,%2,%3};"
        : "+f"(c[0]), "+f"(c[1]), "+f"(c[2]), "+f"(c[3])
        : "r"(a[0]), "r"(a[1]), "r"(a[2]), "r"(a[3]), "r"(b0), "r"(b1));
}
#define CP_ASYNC16(dst, src) \
    asm volatile("cp.async.cg.shared.global [%0], [%1], 16;" :: "r"(dst), "l"(src))
#define CP_COMMIT() asm volatile("cp.async.commit_group;")
#define CP_WAIT(n)  asm volatile("cp.async.wait_group %0;" :: "n"(n))

// =================================================================
// Stage 1: L2-normalize; 2 rows per warp (R14/R15 verbatim, 9.1us).
// =================================================================
__global__ void norm_kernel(const float* __restrict__ ctx) {
    int gwarp = (blockIdx.x * blockDim.x + threadIdx.x) >> 5;
    int lane  = threadIdx.x & 31;
    if (gwarp >= NB * NL) return;

    int vr0 = 2 * gwarp;
    int vr1 = vr0 + 1;
    int wh0 = vr0 >> 14, rr0 = vr0 & 16383;
    int wh1 = vr1 >> 14, rr1 = vr1 & 16383;
    int b0 = rr0 >> 11, l0 = rr0 & 2047;
    int b1_ = rr1 >> 11, l1 = rr1 & 2047;

    const float4* src0 =
        (const float4*)(ctx + ((size_t)(b0 * 2 + wh0) * NL + l0) * ND);
    const float4* src1 =
        (const float4*)(ctx + ((size_t)(b1_ * 2 + wh1) * NL + l1) * ND);
    float4 v0 = src0[lane];
    float4 v1 = src1[lane];

    float s0 = v0.x * v0.x + v0.y * v0.y + v0.z * v0.z + v0.w * v0.w;
    float s1 = v1.x * v1.x + v1.y * v1.y + v1.z * v1.z + v1.w * v1.w;
#pragma unroll
    for (int o = 16; o; o >>= 1) {
        s0 += __shfl_xor_sync(0xffffffffu, s0, o);
        s1 += __shfl_xor_sync(0xffffffffu, s1, o);
    }
    float inv0 = 1.0f / fmaxf(sqrtf(s0), EPSN);
    float inv1 = 1.0f / fmaxf(sqrtf(s1), EPSN);
    float4 o0 = make_float4(v0.x * inv0, v0.y * inv0, v0.z * inv0, v0.w * inv0);
    float4 o1 = make_float4(v1.x * inv1, v1.y * inv1, v1.z * inv1, v1.w * inv1);

    ((float4*)((wh0 ? g_en : g_cn) + (size_t)rr0 * ND))[lane] = o0;
    ((float4*)((wh1 ? g_en : g_cn) + (size_t)rr1 * ND))[lane] = o1;
    {
        __nv_bfloat16* bd = (wh0 ? g_enbf : g_cnbf) + (size_t)rr0 * ND;
        __nv_bfloat162* hp = (__nv_bfloat162*)(bd + lane * 4);
        hp[0] = __halves2bfloat162(__float2bfloat16(o0.x), __float2bfloat16(o0.y));
        hp[1] = __halves2bfloat162(__float2bfloat16(o0.z), __float2bfloat16(o0.w));
    }
    {
        __nv_bfloat16* bd = (wh1 ? g_enbf : g_cnbf) + (size_t)rr1 * ND;
        __nv_bfloat162* hp = (__nv_bfloat162*)(bd + lane * 4);
        hp[0] = __halves2bfloat162(__float2bfloat16(o1.x), __float2bfloat16(o1.y));
        hp[1] = __halves2bfloat162(__float2bfloat16(o1.z), __float2bfloat16(o1.w));
    }
}

// =================================================================
// Stage 2: tensor-core per-row MLP scalar (R15 verbatim, ~13us).
// =================================================================
#define LDB 272
#define TC_AHI 0
#define TC_ALO 34816
#define TC_BHI 69632
#define TC_BLO 104448
#define TC_B1  139264
#define TC_W2  139776
#define TC_RED 140288
#define TC_TOTAL 141312

__global__ __launch_bounds__(256, 1) void smlp_tc_kernel(
    const float* __restrict__ W1, const float* __restrict__ b1,
    const float* __restrict__ W2) {
    extern __shared__ char smc[];
    float* b1s = (float*)(smc + TC_B1);
    float* w2s = (float*)(smc + TC_W2);
    float* red = (float*)(smc + TC_RED);

    int tid = threadIdx.x, w = tid >> 5, lane = tid & 31;
    int wy = w >> 1, wx = w & 1;
    int g = lane >> 2, t = lane & 3;

    int vr0 = blockIdx.x * 128;
    const float* rowsrc = (vr0 < NB * NL)
        ? g_cn + (size_t)vr0 * ND
        : g_en + (size_t)(vr0 - NB * NL) * ND;

    for (int i = tid; i < 16384; i += 256) {
        int k = i >> 7, n = i & 127;
        float x = W1[k * 128 + n];
        __nv_bfloat16 hi = __float2bfloat16(x);
        __nv_bfloat16 lo = __float2bfloat16(x - __bfloat162float(hi));
        *(__nv_bfloat16*)(smc + TC_BHI + n * LDB + k * 2) = hi;
        *(__nv_bfloat16*)(smc + TC_BLO + n * LDB + k * 2) = lo;
    }
    for (int i = tid; i < 16384; i += 256) {
        int r = i >> 7, k = i & 127;
        float x = rowsrc[(size_t)r * ND + k];
        __nv_bfloat16 hi = __float2bfloat16(x);
        __nv_bfloat16 lo = __float2bfloat16(x - __bfloat162float(hi));
        *(__nv_bfloat16*)(smc + TC_AHI + r * LDB + k * 2) = hi;
        *(__nv_bfloat16*)(smc + TC_ALO + r * LDB + k * 2) = lo;
    }
    if (tid < 128) { b1s[tid] = b1[tid]; w2s[tid] = W2[tid]; }
    __syncthreads();

    uint32_t sb = smem_u32(smc);
    uint32_t aoff = (32 * wy + (lane & 15)) * LDB + (lane >> 4) * 16;
    uint32_t boff = (lane & 7) * LDB + ((lane >> 3) & 1) * 16 +
                    (lane >> 4) * 8 * LDB + wx * 64 * LDB;

    float acc[2][8][4];
#pragma unroll
    for (int f = 0; f < 2; ++f)
#pragma unroll
        for (int j = 0; j < 8; ++j)
#pragma unroll
            for (int c = 0; c < 4; ++c) acc[f][j][c] = 0.0f;

#pragma unroll
    for (int kc = 0; kc < 8; ++kc) {
        uint32_t ahi0[4], ahi1[4], alo0[4], alo1[4];
        ldm4(ahi0, sb + TC_AHI + aoff + kc * 32);
        ldm4(ahi1, sb + TC_AHI + aoff + 16 * LDB + kc * 32);
        ldm4(alo0, sb + TC_ALO + aoff + kc * 32);
        ldm4(alo1, sb + TC_ALO + aoff + 16 * LDB + kc * 32);
#pragma unroll
        for (int j2 = 0; j2 < 4; ++j2) {
            uint32_t bh[4], bl[4];
            ldm4(bh, sb + TC_BHI + boff + j2 * 16 * LDB + kc * 32);
            ldm4(bl, sb + TC_BLO + boff + j2 * 16 * LDB + kc * 32);
            mma16816s(acc[0][2 * j2],     ahi0, bh[0], bh[1]);
            mma16816s(acc[0][2 * j2 + 1], ahi0, bh[2], bh[3]);
            mma16816s(acc[1][2 * j2],     ahi1, bh[0], bh[1]);
            mma16816s(acc[1][2 * j2 + 1], ahi1, bh[2], bh[3]);
            mma16816s(acc[0][2 * j2],     ahi0, bl[0], bl[1]);
            mma16816s(acc[0][2 * j2 + 1], ahi0, bl[2], bl[3]);
            mma16816s(acc[1][2 * j2],     ahi1, bl[0], bl[1]);
            mma16816s(acc[1][2 * j2 + 1], ahi1, bl[2], bl[3]);
            mma16816s(acc[0][2 * j2],     alo0, bh[0], bh[1]);
            mma16816s(acc[0][2 * j2 + 1], alo0, bh[2], bh[3]);
            mma16816s(acc[1][2 * j2],     alo1, bh[0], bh[1]);
            mma16816s(acc[1][2 * j2 + 1], alo1, bh[2], bh[3]);
        }
    }

    float b1r[16], w2r[16];
#pragma unroll
    for (int j = 0; j < 8; ++j)
#pragma unroll
        for (int c = 0; c < 2; ++c) {
            int col = wx * 64 + j * 8 + 2 * t + c;
            b1r[j * 2 + c] = b1s[col];
            w2r[j * 2 + c] = w2s[col];
        }

#pragma unroll
    for (int f = 0; f < 2; ++f)
#pragma unroll
        for (int h = 0; h < 2; ++h) {
            float p = 0.0f;
#pragma unroll
            for (int j = 0; j < 8; ++j)
#pragma unroll
                for (int c = 0; c < 2; ++c) {
                    float v = acc[f][j][2 * h + c] + b1r[j * 2 + c];
                    p += fmaxf(v, 0.0f) * w2r[j * 2 + c];
                }
            p += __shfl_xor_sync(0xffffffffu, p, 1);
            p += __shfl_xor_sync(0xffffffffu, p, 2);
            if (t == 0) red[(32 * wy + 16 * f + 8 * h + g) * 2 + wx] = p;
        }
    __syncthreads();
    if (tid < 128) {
        float s = red[tid * 2] + red[tid * 2 + 1];
        int vr = vr0 + tid;
        if (vr < NB * NL) g_scn[vr] = s;
        else              g_sen[vr - NB * NL] = s;
    }
}

// =================================================================
// Stage 3: HMMA sim-GEMM + fused argmax, 512 threads / 16 warps.
// SINGLE DELTA vs the R15 pass: warp tile 16x64 (wy=w>>1 in 0..7
// selects a 16-row slot; wx=w&1 selects 64 cols). Each warp = ONE
// A fragment (the proven kernel's af[...][0] path); all B/epilogue/
// rescore addressing is the proven code with halved row blocks.
// =================================================================
#define SM_AT   0                           // 34816
#define SM_BT0  34816                       // 3 buffers x 34816
#define SM_CS   139264                      // 128*48*4 = 24576
#define SM_CI   163840                      // 24576
#define SM_CNT  188416                      // 512
#define SM_HM   188928                      // 1024
#define SM_SIM_TOTAL 189952

__global__ __launch_bounds__(512, 1) void simarg_kernel(
    const float* __restrict__ b2, float* __restrict__ out) {
    extern __shared__ char smc[];
    float* candV = (float*)(smc + SM_CS);
    int*   candI = (int*)(smc + SM_CI);
    int*   cnt   = (int*)(smc + SM_CNT);
    float* hmax  = (float*)(smc + SM_HM);

    int tid = threadIdx.x, w = tid >> 5, lane = tid & 31;
    int wy = w >> 1, wx = w & 1;      // 8 row-slots x 2 col-slots
    int g = lane >> 2, t = lane & 3;
    int b = blockIdx.y, l0 = blockIdx.x * 128;

    if (tid < 128) cnt[tid] = 0;

    // load A tile (proven copy pattern, 512-thread stride)
    const uint4* asrc = (const uint4*)(g_cnbf + ((size_t)b * NL + l0) * ND);
#pragma unroll
    for (int i = tid; i < 2048; i += 512) {
        int row = i >> 4, c = i & 15;
        *(uint4*)(smc + SM_AT + row * LDB + c * 16) = asrc[row * 16 + c];
    }

    const char* esrc = (const char*)(g_enbf + (size_t)b * NL * ND);
    uint32_t sb = smem_u32(smc);

    // prefetch B tiles 0 and 1
#pragma unroll
    for (int q = 0; q < 2; ++q) {
#pragma unroll
        for (int i = tid; i < 2048; i += 512) {
            int row = i >> 4, c = i & 15;
            CP_ASYNC16(sb + SM_BT0 + q * 34816 + row * LDB + c * 16,
                       esrc + ((size_t)q * 128 + row) * 256 + c * 16);
        }
        CP_COMMIT();
    }

    // A fragment: rows 16*wy + (lane&15), k-half via lane>>4
    uint32_t aaddr = sb + SM_AT + ((16 * wy + (lane & 15)) * LDB + (lane >> 4) * 16);
    // B x4 base (proven): 2 n-blocks per ldm4
    uint32_t boff = (lane & 7) * LDB + ((lane >> 3) & 1) * 16 + (lane >> 4) * 8 * LDB;

    float rmax[2] = {-2.0f, -2.0f};

    for (int mt = 0; mt < 16; ++mt) {
        if (mt < 15) { CP_WAIT(1); } else { CP_WAIT(0); }
        __syncthreads();

        uint32_t bbase = sb + SM_BT0 + (mt % 3) * 34816 + boff + wx * 64 * LDB;

        float acc[8][4];
#pragma unroll
        for (int j = 0; j < 8; ++j)
#pragma unroll
            for (int c = 0; c < 4; ++c) acc[j][c] = 0.0f;

#pragma unroll
        for (int kc = 0; kc < 8; ++kc) {
            uint32_t a0[4];
            ldm4(a0, aaddr + kc * 32);
#pragma unroll
            for (int j2 = 0; j2 < 4; ++j2) {
                uint32_t bb[4];
                ldm4(bb, bbase + j2 * 16 * LDB + kc * 32);
                mma16816s(acc[2 * j2],     a0, bb[0], bb[1]);
                mma16816s(acc[2 * j2 + 1], a0, bb[2], bb[3]);
            }
        }

        // epilogue: running max + candidate append (proven math)
#pragma unroll
        for (int h = 0; h < 2; ++h) {
            float tm = -2.0f;
#pragma unroll
            for (int j = 0; j < 8; ++j)
                tm = fmaxf(tm, fmaxf(acc[j][2 * h], acc[j][2 * h + 1]));
            tm = fmaxf(tm, __shfl_xor_sync(0xffffffffu, tm, 1));
            tm = fmaxf(tm, __shfl_xor_sync(0xffffffffu, tm, 2));
            float nm = fmaxf(rmax[h], tm);
            rmax[h] = nm;
            float thr = nm - MARGIN;
            int r = 16 * wy + 8 * h + g;
#pragma unroll
            for (int j = 0; j < 8; ++j)
#pragma unroll
                for (int c = 0; c < 2; ++c) {
                    float v = acc[j][2 * h + c];
                    if (v >= thr) {
                        int pos = atomicAdd(&cnt[r], 1);
                        if (pos < CCAP) {
                            candV[r * CCAP + pos] = v;
                            candI[r * CCAP + pos] =
                                mt * 128 + wx * 64 + j * 8 + 2 * t + c;
                        }
                    }
                }
        }
        __syncthreads();  // all reads of buf (mt%3) done

        if (mt + 2 < 16) {
            int nb_ = SM_BT0 + ((mt + 2) % 3) * 34816;
#pragma unroll
            for (int i = tid; i < 2048; i += 512) {
                int row = i >> 4, c = i & 15;
                CP_ASYNC16(sb + nb_ + row * LDB + c * 16,
                           esrc + ((size_t)(mt + 2) * 128 + row) * 256 + c * 16);
            }
            CP_COMMIT();
        }
    }

    // publish per-warp row maxima (2 wx warps per row)
    if (t == 0) {
#pragma unroll
        for (int h = 0; h < 2; ++h)
            hmax[(16 * wy + 8 * h + g) * 2 + wx] = rmax[h];
    }
    __syncthreads();

    // filter + exact fp32 rescore: 4 threads per row; direct output
    {
        int r = tid >> 2;
        float Mb = fmaxf(hmax[r * 2], hmax[r * 2 + 1]);
        float thr = Mb - MARGIN;
        int n = min(cnt[r], CCAP);
        float bv = -1e30f;
        int bi = 0x7fffffff;
        const float4* xa = (const float4*)(g_cn + ((size_t)b * NL + l0 + r) * ND);
        for (int e = (tid & 3); e < n; e += 4) {
            if (candV[r * CCAP + e] < thr) continue;
            int m = candI[r * CCAP + e];
            const float4* xb = (const float4*)(g_en + ((size_t)b * NL + m) * ND);
            float s0 = 0, s1 = 0, s2 = 0, s3 = 0;
#pragma unroll
            for (int q = 0; q < 32; ++q) {
                float4 A = xa[q];
                float4 Bv = xb[q];
                s0 += A.x * Bv.x; s1 += A.y * Bv.y;
                s2 += A.z * Bv.z; s3 += A.w * Bv.w;
            }
            float s = (s0 + s1) + (s2 + s3);
            if (s > bv || (s == bv && m < bi)) { bv = s; bi = m; }
        }
        __syncthreads();
        candV[tid] = bv;    // 512 floats, region holds 6144
        candI[tid] = bi;
        __syncthreads();
        if (tid < 128) {
            float bvf = candV[tid * 4];
            int bif = candI[tid * 4];
#pragma unroll
            for (int q = 1; q < 4; ++q) {
                float v = candV[tid * 4 + q];
                int ix = candI[tid * 4 + q];
                if (v > bvf || (v == bvf && ix < bif)) { bvf = v; bif = ix; }
            }
            out[b * NL + l0 + tid] = g_scn[b * NL + l0 + tid] +
                                     g_sen[b * NL + bif] + 2.0f * b2[0];
        }
    }
}

// =================================================================
// launch
// =================================================================
extern "C" void kernel_launch(void* const* d_in, const int* in_sizes, int n_in,
                              void* d_out, int out_size) {
    const float* context = (const float*)d_in[0];
    const float* W1      = (const float*)d_in[1];
    const float* b1      = (const float*)d_in[2];
    const float* W2      = (const float*)d_in[3];
    const float* b2      = (const float*)d_in[4];
    float* out           = (float*)d_out;

    {
        int warps = NB * NL;
        int threads = 256;
        int blocks = (warps * 32 + threads - 1) / threads;
        norm_kernel<<<blocks, threads>>>(context);
    }
    {
        cudaFuncSetAttribute(smlp_tc_kernel,
                             cudaFuncAttributeMaxDynamicSharedMemorySize,
                             TC_TOTAL);
        smlp_tc_kernel<<<2 * NB * NL / 128, 256, TC_TOTAL>>>(W1, b1, W2);
    }
    {
        cudaFuncSetAttribute(simarg_kernel,
                             cudaFuncAttributeMaxDynamicSharedMemorySize,
                             SM_SIM_TOTAL);
        dim3 grid(NL / 128, NB);
        simarg_kernel<<<grid, 512, SM_SIM_TOTAL>>>(b2, out);
    }
}